// round 2
// baseline (speedup 1.0000x reference)
#include <cuda_runtime.h>
#include <math.h>
#include <stdint.h>

#define BB 128
#define VV 128000
#define NBINS 8192
#define BIN_SCALE 256.0f          // bin width 1/256 over d = m - x
#define CAND_CAP 2048
#define NTH 1024
#define FINFO_MIN -3.4028234663852886e38f

struct Smem {
    unsigned int        hist_cnt[NBINS];   // becomes inclusive count prefix
    float               hist_exp[NBINS];
    double              exp_pref[NBINS];   // inclusive exp-mass prefix (desc value order)
    unsigned long long  cand[CAND_CAP];    // top-k candidates: key = flip(x)<<32 | ~idx
    float               pbin[CAND_CAP];    // values in the top-p cutoff bin
    double              bufA[CAND_CAP];
    double              bufB[CAND_CAP];
    double              redd[NTH];
    float               redf[NTH];
    unsigned int        scanu[NTH];
    // scalars
    int   cb_p, cb_k;
    unsigned int candCount, pbinCount;
    int   cntA;
    float logS;
    float xmin_kept;
    int   token;
    float xtok;
};

__device__ __forceinline__ unsigned flipf(float f) {
    unsigned u = __float_as_uint(f);
    return u ^ ((u >> 31) ? 0xFFFFFFFFu : 0x80000000u);
}
__device__ __forceinline__ float unflipf(unsigned u) {
    unsigned b = u ^ ((u & 0x80000000u) ? 0x80000000u : 0xFFFFFFFFu);
    return __uint_as_float(b);
}

// Inclusive double scan over a[0..n2), n2 = pow2 <= 2048.
// ALL NTH threads must call; barriers are unconditional.
__device__ void scan_inclusive(double* a, int n2) {
    int tid = threadIdx.x;
    for (int off = 1; off < n2; off <<= 1) {
        double v0 = 0.0, v1 = 0.0;
        int i0 = tid, i1 = tid + NTH;
        bool h0 = i0 < n2, h1 = i1 < n2;
        if (h0) { v0 = a[i0]; if (i0 >= off) v0 += a[i0 - off]; }
        if (h1) { v1 = a[i1]; if (i1 >= off) v1 += a[i1 - off]; }
        __syncthreads();
        if (h0) a[i0] = v0;
        if (h1) a[i1] = v1;
        __syncthreads();
    }
}

__global__ void __launch_bounds__(NTH, 1)
sampler_kernel(const float* __restrict__ logits,
               const float* __restrict__ temps,
               const int*   __restrict__ topks,
               const float* __restrict__ topps,
               const float* __restrict__ minps,
               const float* __restrict__ us,
               float* __restrict__ out)
{
    extern __shared__ char smem_raw[];
    Smem* sm = reinterpret_cast<Smem*>(smem_raw);
    const int row = blockIdx.x;
    const int tid = threadIdx.x;
    const float* __restrict__ rowp = logits + (size_t)row * VV;

    const float temp  = temps[row];
    const int   K     = topks[row];
    const float top_p = topps[row];
    const float min_p = minps[row];
    const float u     = us[row];

    // -------- init --------
    for (int i = tid; i < NBINS; i += NTH) { sm->hist_cnt[i] = 0u; sm->hist_exp[i] = 0.0f; }
    if (tid == 0) {
        sm->candCount = 0u; sm->pbinCount = 0u; sm->cntA = 0;
        sm->cb_p = NBINS - 1; sm->cb_k = NBINS - 1;
    }

    // -------- pass 1: online max + sum(exp) --------
    float  mt = -INFINITY;
    float  st = 0.0f;
    for (int i = tid; i < VV; i += NTH) {
        float x = rowp[i] / temp;
        if (x > mt) { st = st * expf(mt - x) + 1.0f; mt = x; }
        else        { st += expf(x - mt); }
    }
    sm->redf[tid] = mt;
    sm->redd[tid] = (double)st;
    __syncthreads();
    for (int off = NTH / 2; off > 0; off >>= 1) {
        if (tid < off) {
            float  m1 = sm->redf[tid], m2 = sm->redf[tid + off];
            double s1 = sm->redd[tid], s2 = sm->redd[tid + off];
            float  mm = fmaxf(m1, m2);
            sm->redd[tid] = s1 * exp((double)(m1 - mm)) + s2 * exp((double)(m2 - mm));
            sm->redf[tid] = mm;
        }
        __syncthreads();
    }
    const float m = sm->redf[0];
    __syncthreads();

    // -------- pass 2: histogram over d = m - x --------
    for (int i = tid; i < VV; i += NTH) {
        float x = rowp[i] / temp;
        float d = m - x;
        int b = (int)(d * BIN_SCALE);
        b = b < 0 ? 0 : (b > NBINS - 1 ? NBINS - 1 : b);
        atomicAdd(&sm->hist_cnt[b], 1u);
        atomicAdd(&sm->hist_exp[b], expf(-d));
    }
    __syncthreads();

    // -------- prefix scans over bins (8 bins/thread) --------
    const int base = tid * (NBINS / NTH);
    unsigned lc[NBINS / NTH];
    double   le[NBINS / NTH];
    unsigned crun = 0; double erun = 0.0;
#pragma unroll
    for (int j = 0; j < NBINS / NTH; j++) {
        crun += sm->hist_cnt[base + j];  lc[j] = crun;
        erun += (double)sm->hist_exp[base + j]; le[j] = erun;
    }
    sm->scanu[tid] = crun;
    sm->redd[tid]  = erun;
    __syncthreads();
    for (int off = 1; off < NTH; off <<= 1) {
        unsigned cv = sm->scanu[tid]; double ev = sm->redd[tid];
        unsigned ca = 0; double ea = 0.0;
        if (tid >= off) { ca = sm->scanu[tid - off]; ea = sm->redd[tid - off]; }
        __syncthreads();
        sm->scanu[tid] = cv + ca;
        sm->redd[tid]  = ev + ea;
        __syncthreads();
    }
    {
        unsigned cex = sm->scanu[tid] - crun;
        double   eex = sm->redd[tid]  - erun;
#pragma unroll
        for (int j = 0; j < NBINS / NTH; j++) {
            sm->hist_cnt[base + j] = lc[j] + cex;     // inclusive count prefix
            sm->exp_pref[base + j] = le[j] + eex;     // inclusive exp prefix
        }
    }
    __syncthreads();

    const double Zh = sm->exp_pref[NBINS - 1];
    const double P  = (double)top_p * Zh;             // top-p mass threshold (exp units)

    // -------- locate cutoff bins --------
#pragma unroll
    for (int j = 0; j < NBINS / NTH; j++) {
        int g = base + j;
        double A = g ? sm->exp_pref[g - 1] : 0.0;
        double I = sm->exp_pref[g];
        if (A <= P && P < I) sm->cb_p = g;
        unsigned cA = g ? sm->hist_cnt[g - 1] : 0u;
        unsigned cI = sm->hist_cnt[g];
        if (cA < (unsigned)K && (unsigned)K <= cI) sm->cb_k = g;
    }
    __syncthreads();
    const int    cb_p  = sm->cb_p;
    const int    cb_k  = sm->cb_k;
    const double A_cbp = cb_p ? sm->exp_pref[cb_p - 1] : 0.0;

    // -------- pass 3: collect top-k candidates and top-p cutoff-bin members --------
    for (int i = tid; i < VV; i += NTH) {
        float x = rowp[i] / temp;
        float d = m - x;
        int b = (int)(d * BIN_SCALE);
        b = b < 0 ? 0 : (b > NBINS - 1 ? NBINS - 1 : b);
        if (b <= cb_k) {
            unsigned p = atomicAdd(&sm->candCount, 1u);
            if (p < CAND_CAP) {
                unsigned fu = flipf(x);
                sm->cand[p] = ((unsigned long long)fu << 32) | (unsigned)(~(unsigned)i);
            }
        }
        if (b == cb_p) {
            unsigned q = atomicAdd(&sm->pbinCount, 1u);
            if (q < CAND_CAP) sm->pbin[q] = x;
        }
    }
    __syncthreads();
    const int C   = (int)min(sm->candCount, (unsigned)CAND_CAP);
    const int npb = (int)min(sm->pbinCount, (unsigned)CAND_CAP);

    // -------- bitonic sort candidates descending (value desc, index asc) --------
    int n2 = 1; while (n2 < C) n2 <<= 1;
    for (int i = C + tid; i < n2; i += NTH) sm->cand[i] = 0ull;
    __syncthreads();
    for (int k = 2; k <= n2; k <<= 1)
        for (int j = k >> 1; j > 0; j >>= 1) {
            for (int idx = tid; idx < n2; idx += NTH) {
                int ixj = idx ^ j;
                if (ixj > idx) {
                    unsigned long long a = sm->cand[idx], b2 = sm->cand[ixj];
                    bool up = ((idx & k) == 0);
                    if (up ? (a < b2) : (a > b2)) { sm->cand[idx] = b2; sm->cand[ixj] = a; }
                }
            }
            __syncthreads();
        }

    // -------- bitonic sort cutoff-bin values descending --------
    int n2p = 1; while (n2p < npb) n2p <<= 1;
    for (int i = npb + tid; i < n2p; i += NTH) sm->pbin[i] = -INFINITY;
    __syncthreads();
    for (int k = 2; k <= n2p; k <<= 1)
        for (int j = k >> 1; j > 0; j >>= 1) {
            for (int idx = tid; idx < n2p; idx += NTH) {
                int ixj = idx ^ j;
                if (ixj > idx) {
                    float a = sm->pbin[idx], b2 = sm->pbin[ixj];
                    bool up = ((idx & k) == 0);
                    if (up ? (a < b2) : (a > b2)) { sm->pbin[idx] = b2; sm->pbin[ixj] = a; }
                }
            }
            __syncthreads();
        }

    // -------- sampling over sorted candidates --------
    {
        int i0 = tid, i1 = tid + NTH;
        bool h0 = i0 < n2, h1 = i1 < n2;
        double e0v = 0.0, e1v = 0.0;
        if (h0 && i0 < C) e0v = exp((double)(unflipf((unsigned)(sm->cand[i0] >> 32)) - m));
        if (h1 && i1 < C) e1v = exp((double)(unflipf((unsigned)(sm->cand[i1] >> 32)) - m));
        __syncthreads();
        if (h0) { sm->bufA[i0] = e0v; sm->bufB[i0] = e0v; }
        if (h1) { sm->bufA[i1] = e1v; sm->bufB[i1] = e1v; }
        __syncthreads();
    }
    scan_inclusive(sm->bufA, n2);                 // inclusive cumsum of e
    const double ehead = sm->bufB[0];
    const double thrE  = (double)min_p * ehead;   // min-p threshold (exp units)
    // ---- apply filters (flat two-slot form, uniform barriers) ----
    {
        int i0 = tid, i1 = tid + NTH;
        bool h0 = i0 < n2, h1 = i1 < n2;
        double ps0 = 0.0, ps1 = 0.0;
        if (h0 && i0 < C) {
            double e = sm->bufB[i0];
            double cumex = sm->bufA[i0] - e;
            if (i0 < K && cumex <= P && e >= thrE) ps0 = e;
        }
        if (h1 && i1 < C) {
            double e = sm->bufB[i1];
            double cumex = sm->bufA[i1] - e;
            if (i1 < K && cumex <= P && e >= thrE) ps1 = e;
        }
        __syncthreads();
        if (h0) sm->bufA[i0] = ps0;
        if (h1) sm->bufA[i1] = ps1;
        __syncthreads();
    }
    scan_inclusive(sm->bufA, n2);                 // cdf of filtered ps
    const double total  = sm->bufA[n2 - 1];
    const double target = (double)u * total;
    {
        int cnt = 0;
        for (int idx = tid; idx < C; idx += NTH)
            if (sm->bufA[idx] < target) cnt++;
        if (cnt) atomicAdd(&sm->cntA, cnt);
    }
    __syncthreads();
    if (tid == 0) {
        int s = sm->cntA; if (s > C - 1) s = C - 1;
        unsigned long long key = sm->cand[s];
        sm->token = (int)(~(unsigned)(key & 0xFFFFFFFFull));
        sm->xtok  = unflipf((unsigned)(key >> 32));
        sm->cntA  = 0;                            // reset for refinement count
    }
    __syncthreads();

    // -------- top-p cutoff-bin refinement (exact threshold + kept mass) --------
    {
        int i0 = tid, i1 = tid + NTH;
        bool h0 = i0 < n2p, h1 = i1 < n2p;
        double e0v = 0.0, e1v = 0.0;
        if (h0 && i0 < npb) e0v = exp((double)(sm->pbin[i0] - m));
        if (h1 && i1 < npb) e1v = exp((double)(sm->pbin[i1] - m));
        __syncthreads();
        if (h0) { sm->bufA[i0] = e0v; sm->bufB[i0] = e0v; }
        if (h1) { sm->bufA[i1] = e1v; sm->bufB[i1] = e1v; }
        __syncthreads();
    }
    scan_inclusive(sm->bufA, n2p);
    {
        int cnt = 0;
        for (int idx = tid; idx < npb; idx += NTH) {
            double cumex = A_cbp + (sm->bufA[idx] - sm->bufB[idx]);
            if (cumex <= P) cnt++;
        }
        if (cnt) atomicAdd(&sm->cntA, cnt);
    }
    __syncthreads();
    if (tid == 0) {
        int t = sm->cntA;
        double S = A_cbp + (t > 0 ? sm->bufA[t - 1] : 0.0);
        sm->logS = (float)log(S);
        sm->xmin_kept = (t > 0) ? sm->pbin[t - 1] : INFINITY;
    }
    __syncthreads();
    const float logS = sm->logS;
    const float xmin = sm->xmin_kept;

    // -------- pass 4: write logprobs --------
    float* __restrict__ lp_out = out + BB + (size_t)row * VV;
    for (int i = tid; i < VV; i += NTH) {
        float x = rowp[i] / temp;
        float d = m - x;
        int b = (int)(d * BIN_SCALE);
        b = b < 0 ? 0 : (b > NBINS - 1 ? NBINS - 1 : b);
        bool kept = (b < cb_p) || (b == cb_p && x >= xmin);
        lp_out[i] = kept ? (x - m) - logS : FINFO_MIN;
    }
    if (tid == 0) {
        out[row] = (float)sm->token;
        out[BB + (size_t)BB * VV + row] = (sm->xtok - m) - logS;
    }
}

extern "C" void kernel_launch(void* const* d_in, const int* in_sizes, int n_in,
                              void* d_out, int out_size)
{
    const float* logits = (const float*)d_in[0];
    const float* temps  = (const float*)d_in[1];
    const int*   topks  = (const int*)  d_in[2];
    const float* topps  = (const float*)d_in[3];
    const float* minps  = (const float*)d_in[4];
    const float* us     = (const float*)d_in[5];
    float* out = (float*)d_out;

    cudaFuncSetAttribute(sampler_kernel,
                         cudaFuncAttributeMaxDynamicSharedMemorySize,
                         (int)sizeof(Smem));
    sampler_kernel<<<BB, NTH, sizeof(Smem)>>>(logits, temps, topks, topps, minps, us, out);
}

// round 4
// speedup vs baseline: 1.9155x; 1.9155x over previous
#include <cuda_runtime.h>
#include <math.h>
#include <stdint.h>

#define BB 128
#define VV 128000
#define VV4 (VV / 4)
#define NBINS 8192
#define BIN_SCALE 256.0f          // bin width 1/256 over d = m - x
#define CAND_CAP 2048
#define NTH 1024
#define FINFO_MIN -3.4028234663852886e38f

struct Smem {
    unsigned int        hist_cnt[NBINS];   // becomes inclusive count prefix
    float               hist_exp[NBINS];
    double              exp_pref[NBINS];   // inclusive exp-mass prefix (desc value order)
    unsigned long long  cand[CAND_CAP];    // top-k candidates: key = flip(x)<<32 | ~idx
    float               pbin[CAND_CAP];    // values in the top-p cutoff bin
    double              bufA[CAND_CAP];
    double              bufB[CAND_CAP];
    double              redd[NTH];
    float               redf[NTH];
    unsigned int        scanu[NTH];
    // scalars
    int   cb_p, cb_k;
    unsigned int candCount, pbinCount;
    int   cntA;
    float logS;
    float xmin_kept;
    int   token;
    float xtok;
};

__device__ __forceinline__ unsigned flipf(float f) {
    unsigned u = __float_as_uint(f);
    return u ^ ((u >> 31) ? 0xFFFFFFFFu : 0x80000000u);
}
__device__ __forceinline__ float unflipf(unsigned u) {
    unsigned b = u ^ ((u & 0x80000000u) ? 0x80000000u : 0xFFFFFFFFu);
    return __uint_as_float(b);
}
__device__ __forceinline__ int binof(float d) {
    int b = (int)(d * BIN_SCALE);
    return b < 0 ? 0 : (b > NBINS - 1 ? NBINS - 1 : b);
}

// Inclusive double scan over a[0..n2), n2 = pow2 <= 2048.
// ALL NTH threads must call; barriers are unconditional.
__device__ void scan_inclusive(double* a, int n2) {
    int tid = threadIdx.x;
    for (int off = 1; off < n2; off <<= 1) {
        double v0 = 0.0, v1 = 0.0;
        int i0 = tid, i1 = tid + NTH;
        bool h0 = i0 < n2, h1 = i1 < n2;
        if (h0) { v0 = a[i0]; if (i0 >= off) v0 += a[i0 - off]; }
        if (h1) { v1 = a[i1]; if (i1 >= off) v1 += a[i1 - off]; }
        __syncthreads();
        if (h0) a[i0] = v0;
        if (h1) a[i1] = v1;
        __syncthreads();
    }
}

__global__ void __launch_bounds__(NTH, 1)
sampler_kernel(const float* __restrict__ logits,
               const float* __restrict__ temps,
               const int*   __restrict__ topks,
               const float* __restrict__ topps,
               const float* __restrict__ minps,
               const float* __restrict__ us,
               float* __restrict__ out)
{
    extern __shared__ char smem_raw[];
    Smem* sm = reinterpret_cast<Smem*>(smem_raw);
    const int row = blockIdx.x;
    const int tid = threadIdx.x;
    const int lane = tid & 31;
    const int wid  = tid >> 5;
    const float* __restrict__ rowp = logits + (size_t)row * VV;
    const float4* __restrict__ rowp4 = reinterpret_cast<const float4*>(rowp);

    const float temp  = temps[row];
    const int   K     = topks[row];
    const float top_p = topps[row];
    const float min_p = minps[row];
    const float u     = us[row];

    // -------- init --------
    for (int i = tid; i < NBINS; i += NTH) { sm->hist_cnt[i] = 0u; sm->hist_exp[i] = 0.0f; }
    if (tid == 0) {
        sm->candCount = 0u; sm->pbinCount = 0u; sm->cntA = 0;
        sm->cb_p = NBINS - 1; sm->cb_k = NBINS - 1;
    }

    // -------- pass 1: max over raw logits (division by positive temp is monotone,
    //          so max(logit)/temp == max(logit/temp) bit-exactly) --------
    float mt = -INFINITY;
    for (int i = tid; i < VV4; i += NTH) {
        float4 v = rowp4[i];
        mt = fmaxf(mt, fmaxf(fmaxf(v.x, v.y), fmaxf(v.z, v.w)));
    }
#pragma unroll
    for (int o = 16; o > 0; o >>= 1) mt = fmaxf(mt, __shfl_xor_sync(0xFFFFFFFFu, mt, o));
    if (lane == 0) sm->redf[wid] = mt;
    __syncthreads();
    if (tid < 32) {
        float v = sm->redf[tid];
#pragma unroll
        for (int o = 16; o > 0; o >>= 1) v = fmaxf(v, __shfl_xor_sync(0xFFFFFFFFu, v, o));
        if (tid == 0) sm->redf[0] = v;
    }
    __syncthreads();
    const float m = sm->redf[0] / temp;
    __syncthreads();

    // -------- pass 2: histogram over d = m - x (float4, 4-way ILP) --------
    for (int i = tid; i < VV4; i += NTH) {
        float4 v = rowp4[i];
        float x0 = v.x / temp, x1 = v.y / temp, x2 = v.z / temp, x3 = v.w / temp;
        float d0 = m - x0, d1 = m - x1, d2 = m - x2, d3 = m - x3;
        float e0 = expf(-d0), e1 = expf(-d1), e2 = expf(-d2), e3 = expf(-d3);
        int b0 = binof(d0), b1 = binof(d1), b2 = binof(d2), b3 = binof(d3);
        atomicAdd(&sm->hist_cnt[b0], 1u); atomicAdd(&sm->hist_exp[b0], e0);
        atomicAdd(&sm->hist_cnt[b1], 1u); atomicAdd(&sm->hist_exp[b1], e1);
        atomicAdd(&sm->hist_cnt[b2], 1u); atomicAdd(&sm->hist_exp[b2], e2);
        atomicAdd(&sm->hist_cnt[b3], 1u); atomicAdd(&sm->hist_exp[b3], e3);
    }
    __syncthreads();

    // -------- prefix scans over bins (8 bins/thread) --------
    const int base = tid * (NBINS / NTH);
    unsigned lc[NBINS / NTH];
    double   le[NBINS / NTH];
    unsigned crun = 0; double erun = 0.0;
#pragma unroll
    for (int j = 0; j < NBINS / NTH; j++) {
        crun += sm->hist_cnt[base + j];  lc[j] = crun;
        erun += (double)sm->hist_exp[base + j]; le[j] = erun;
    }
    sm->scanu[tid] = crun;
    sm->redd[tid]  = erun;
    __syncthreads();
    for (int off = 1; off < NTH; off <<= 1) {
        unsigned cv = sm->scanu[tid]; double ev = sm->redd[tid];
        unsigned ca = 0; double ea = 0.0;
        if (tid >= off) { ca = sm->scanu[tid - off]; ea = sm->redd[tid - off]; }
        __syncthreads();
        sm->scanu[tid] = cv + ca;
        sm->redd[tid]  = ev + ea;
        __syncthreads();
    }
    {
        unsigned cex = sm->scanu[tid] - crun;
        double   eex = sm->redd[tid]  - erun;
#pragma unroll
        for (int j = 0; j < NBINS / NTH; j++) {
            sm->hist_cnt[base + j] = lc[j] + cex;     // inclusive count prefix
            sm->exp_pref[base + j] = le[j] + eex;     // inclusive exp prefix
        }
    }
    __syncthreads();

    const double Zh = sm->exp_pref[NBINS - 1];
    const double P  = (double)top_p * Zh;             // top-p mass threshold (exp units)

    // -------- locate cutoff bins --------
#pragma unroll
    for (int j = 0; j < NBINS / NTH; j++) {
        int g = base + j;
        double A = g ? sm->exp_pref[g - 1] : 0.0;
        double I = sm->exp_pref[g];
        if (A <= P && P < I) sm->cb_p = g;
        unsigned cA = g ? sm->hist_cnt[g - 1] : 0u;
        unsigned cI = sm->hist_cnt[g];
        if (cA < (unsigned)K && (unsigned)K <= cI) sm->cb_k = g;
    }
    __syncthreads();
    const int    cb_p  = sm->cb_p;
    const int    cb_k  = sm->cb_k;
    const double A_cbp = cb_p ? sm->exp_pref[cb_p - 1] : 0.0;

    // -------- pass 3: collect top-k candidates and top-p cutoff-bin members --------
    for (int i = tid; i < VV4; i += NTH) {
        float4 v = rowp4[i];
        float xs[4];
        xs[0] = v.x / temp; xs[1] = v.y / temp; xs[2] = v.z / temp; xs[3] = v.w / temp;
#pragma unroll
        for (int j = 0; j < 4; j++) {
            float x = xs[j];
            int b = binof(m - x);
            if (b <= cb_k) {
                unsigned p = atomicAdd(&sm->candCount, 1u);
                if (p < CAND_CAP) {
                    unsigned fu = flipf(x);
                    unsigned gidx = (unsigned)(4 * i + j);
                    sm->cand[p] = ((unsigned long long)fu << 32) | (unsigned)(~gidx);
                }
            }
            if (b == cb_p) {
                unsigned q = atomicAdd(&sm->pbinCount, 1u);
                if (q < CAND_CAP) sm->pbin[q] = x;
            }
        }
    }
    __syncthreads();
    const int C   = (int)min(sm->candCount, (unsigned)CAND_CAP);
    const int npb = (int)min(sm->pbinCount, (unsigned)CAND_CAP);

    // -------- bitonic sort candidates descending (value desc, index asc) --------
    int n2 = 1; while (n2 < C) n2 <<= 1;
    for (int i = C + tid; i < n2; i += NTH) sm->cand[i] = 0ull;
    __syncthreads();
    for (int k = 2; k <= n2; k <<= 1)
        for (int j = k >> 1; j > 0; j >>= 1) {
            for (int idx = tid; idx < n2; idx += NTH) {
                int ixj = idx ^ j;
                if (ixj > idx) {
                    unsigned long long a = sm->cand[idx], b2 = sm->cand[ixj];
                    bool up = ((idx & k) == 0);
                    if (up ? (a < b2) : (a > b2)) { sm->cand[idx] = b2; sm->cand[ixj] = a; }
                }
            }
            __syncthreads();
        }

    // -------- bitonic sort cutoff-bin values descending --------
    int n2p = 1; while (n2p < npb) n2p <<= 1;
    for (int i = npb + tid; i < n2p; i += NTH) sm->pbin[i] = -INFINITY;
    __syncthreads();
    for (int k = 2; k <= n2p; k <<= 1)
        for (int j = k >> 1; j > 0; j >>= 1) {
            for (int idx = tid; idx < n2p; idx += NTH) {
                int ixj = idx ^ j;
                if (ixj > idx) {
                    float a = sm->pbin[idx], b2 = sm->pbin[ixj];
                    bool up = ((idx & k) == 0);
                    if (up ? (a < b2) : (a > b2)) { sm->pbin[idx] = b2; sm->pbin[ixj] = a; }
                }
            }
            __syncthreads();
        }

    // -------- sampling over sorted candidates --------
    {
        int i0 = tid, i1 = tid + NTH;
        bool h0 = i0 < n2, h1 = i1 < n2;
        double e0v = 0.0, e1v = 0.0;
        if (h0 && i0 < C) e0v = exp((double)(unflipf((unsigned)(sm->cand[i0] >> 32)) - m));
        if (h1 && i1 < C) e1v = exp((double)(unflipf((unsigned)(sm->cand[i1] >> 32)) - m));
        __syncthreads();
        if (h0) { sm->bufA[i0] = e0v; sm->bufB[i0] = e0v; }
        if (h1) { sm->bufA[i1] = e1v; sm->bufB[i1] = e1v; }
        __syncthreads();
    }
    scan_inclusive(sm->bufA, n2);                 // inclusive cumsum of e
    const double ehead = sm->bufB[0];
    const double thrE  = (double)min_p * ehead;   // min-p threshold (exp units)
    // ---- apply filters (flat two-slot form, uniform barriers) ----
    {
        int i0 = tid, i1 = tid + NTH;
        bool h0 = i0 < n2, h1 = i1 < n2;
        double ps0 = 0.0, ps1 = 0.0;
        if (h0 && i0 < C) {
            double e = sm->bufB[i0];
            double cumex = sm->bufA[i0] - e;
            if (i0 < K && cumex <= P && e >= thrE) ps0 = e;
        }
        if (h1 && i1 < C) {
            double e = sm->bufB[i1];
            double cumex = sm->bufA[i1] - e;
            if (i1 < K && cumex <= P && e >= thrE) ps1 = e;
        }
        __syncthreads();
        if (h0) sm->bufA[i0] = ps0;
        if (h1) sm->bufA[i1] = ps1;
        __syncthreads();
    }
    scan_inclusive(sm->bufA, n2);                 // cdf of filtered ps
    const double total  = sm->bufA[n2 - 1];
    const double target = (double)u * total;
    {
        int cnt = 0;
        for (int idx = tid; idx < C; idx += NTH)
            if (sm->bufA[idx] < target) cnt++;
        if (cnt) atomicAdd(&sm->cntA, cnt);
    }
    __syncthreads();
    if (tid == 0) {
        int s = sm->cntA; if (s > C - 1) s = C - 1;
        unsigned long long key = sm->cand[s];
        sm->token = (int)(~(unsigned)(key & 0xFFFFFFFFull));
        sm->xtok  = unflipf((unsigned)(key >> 32));
        sm->cntA  = 0;                            // reset for refinement count
    }
    __syncthreads();

    // -------- top-p cutoff-bin refinement (exact threshold + kept mass) --------
    {
        int i0 = tid, i1 = tid + NTH;
        bool h0 = i0 < n2p, h1 = i1 < n2p;
        double e0v = 0.0, e1v = 0.0;
        if (h0 && i0 < npb) e0v = exp((double)(sm->pbin[i0] - m));
        if (h1 && i1 < npb) e1v = exp((double)(sm->pbin[i1] - m));
        __syncthreads();
        if (h0) { sm->bufA[i0] = e0v; sm->bufB[i0] = e0v; }
        if (h1) { sm->bufA[i1] = e1v; sm->bufB[i1] = e1v; }
        __syncthreads();
    }
    scan_inclusive(sm->bufA, n2p);
    {
        int cnt = 0;
        for (int idx = tid; idx < npb; idx += NTH) {
            double cumex = A_cbp + (sm->bufA[idx] - sm->bufB[idx]);
            if (cumex <= P) cnt++;
        }
        if (cnt) atomicAdd(&sm->cntA, cnt);
    }
    __syncthreads();
    if (tid == 0) {
        int t = sm->cntA;
        double S = A_cbp + (t > 0 ? sm->bufA[t - 1] : 0.0);
        sm->logS = (float)log(S);
        sm->xmin_kept = (t > 0) ? sm->pbin[t - 1] : INFINITY;
    }
    __syncthreads();
    const float logS = sm->logS;
    const float xmin = sm->xmin_kept;

    // -------- pass 4: write logprobs (float4) --------
    float4* __restrict__ lp_out4 =
        reinterpret_cast<float4*>(out + BB + (size_t)row * VV);
    for (int i = tid; i < VV4; i += NTH) {
        float4 v = rowp4[i];
        float4 r;
        {
            float x = v.x / temp; int b = binof(m - x);
            bool kept = (b < cb_p) || (b == cb_p && x >= xmin);
            r.x = kept ? (x - m) - logS : FINFO_MIN;
        }
        {
            float x = v.y / temp; int b = binof(m - x);
            bool kept = (b < cb_p) || (b == cb_p && x >= xmin);
            r.y = kept ? (x - m) - logS : FINFO_MIN;
        }
        {
            float x = v.z / temp; int b = binof(m - x);
            bool kept = (b < cb_p) || (b == cb_p && x >= xmin);
            r.z = kept ? (x - m) - logS : FINFO_MIN;
        }
        {
            float x = v.w / temp; int b = binof(m - x);
            bool kept = (b < cb_p) || (b == cb_p && x >= xmin);
            r.w = kept ? (x - m) - logS : FINFO_MIN;
        }
        lp_out4[i] = r;
    }
    if (tid == 0) {
        out[row] = (float)sm->token;
        out[BB + (size_t)BB * VV + row] = (sm->xtok - m) - logS;
    }
}

extern "C" void kernel_launch(void* const* d_in, const int* in_sizes, int n_in,
                              void* d_out, int out_size)
{
    const float* logits = (const float*)d_in[0];
    const float* temps  = (const float*)d_in[1];
    const int*   topks  = (const int*)  d_in[2];
    const float* topps  = (const float*)d_in[3];
    const float* minps  = (const float*)d_in[4];
    const float* us     = (const float*)d_in[5];
    float* out = (float*)d_out;

    cudaFuncSetAttribute(sampler_kernel,
                         cudaFuncAttributeMaxDynamicSharedMemorySize,
                         (int)sizeof(Smem));
    sampler_kernel<<<BB, NTH, sizeof(Smem)>>>(logits, temps, topks, topps, minps, us, out);
}